// round 17
// baseline (speedup 1.0000x reference)
#include <cuda_runtime.h>
#include <math.h>

// Shapes fixed: b=4, h=w=64, c=512, HEADS=8, DIM_HEAD=64.
#define M_TOTAL 16384
#define C_DIM   512
#define NPIX    16384

// Scratch (no cudaMalloc allowed).
__device__ float g_q[M_TOTAL * C_DIM];
__device__ float g_k[M_TOTAL * C_DIM];
__device__ float g_v[M_TOTAL * C_DIM];   // 2 * (x @ Wv^T)
__device__ float g_mid[M_TOTAL * C_DIM]; // scrambled attention output

// ---- tf32 helpers ----
__device__ __forceinline__ unsigned f2tf32(float f) {
    unsigned r; asm("cvt.rna.tf32.f32 %0, %1;" : "=r"(r) : "f"(f)); return r;
}
__device__ __forceinline__ void mma_tf32(float c[4],
    unsigned a0, unsigned a1, unsigned a2, unsigned a3,
    unsigned b0, unsigned b1)
{
    asm("mma.sync.aligned.m16n8k8.row.col.f32.tf32.tf32.f32 "
        "{%0,%1,%2,%3},{%4,%5,%6,%7},{%8,%9},{%0,%1,%2,%3};"
        : "+f"(c[0]), "+f"(c[1]), "+f"(c[2]), "+f"(c[3])
        : "r"(a0), "r"(a1), "r"(a2), "r"(a3), "r"(b0), "r"(b1));
}

// ============================================================================
// Generic tf32 tensor-core GEMM:  C[m,n] = scale * sum_k A[m,k]*W[n,k] (+bias)
// M=16384, N=K=512. Block tile 128x128, 256 threads, warp tile 64x32.
// SMEM: pitch-20 rows (16 k-words + 4 pad) with k-interleave
//   k' = (k&3)*4 + (k>>2)   -> one LDS.128 per row serves both k8 substeps.
// Conflict-free: STS.128 fills, LDS.128 fragment reads (pitch-20 bank walk).
// Double-buffered, one __syncthreads per k16 iteration, register prefetch.
// dst: 0->g_q, 1->g_k, 2->g_v, 3-> A=g_mid, C=Cext (projection).
// ============================================================================
#define PITCH 20

__device__ __forceinline__ uint4 ld_cvt4(const float* p) {
    float4 v = *(const float4*)p;
    uint4 u; u.x = f2tf32(v.x); u.y = f2tf32(v.y); u.z = f2tf32(v.z); u.w = f2tf32(v.w);
    return u;
}
__device__ __forceinline__ void sts_perm(unsigned* buf, int row, int c4, uint4 u) {
    unsigned* p = buf + row * PITCH + c4;   // k' = j*4 + c4  (j = k&3)
    p[0] = u.x; p[4] = u.y; p[8] = u.z; p[12] = u.w;
}

__global__ __launch_bounds__(256, 2) void gemm_tf32_kernel(
    const float* __restrict__ A, const float* __restrict__ W,
    const float* __restrict__ bias, float* __restrict__ Cext,
    int dst, float scale)
{
    __shared__ unsigned sA[2][128 * PITCH];
    __shared__ unsigned sB[2][128 * PITCH];

    const float* Ap = (dst == 3) ? g_mid : A;
    float* C = (dst == 0) ? g_q : (dst == 1) ? g_k : (dst == 2) ? g_v : Cext;

    const int tid = threadIdx.x;
    const int bx  = blockIdx.x;
    const int m0  = (bx >> 2) << 7;          // 128 m-tiles
    const int n0  = (bx & 3)  << 7;          // 4 n-tiles

    // tile loaders: rows lrow and lrow+64, one float4 (k-chunk c4) each
    const int lrow = tid >> 2;
    const int lc4  = tid & 3;                // c' = k>>2
    const float* gA = Ap + (size_t)(m0 + lrow) * C_DIM + (lc4 << 2);
    const float* gB = W  + (size_t)(n0 + lrow) * C_DIM + (lc4 << 2);

    // warp coords
    const int w    = tid >> 5;
    const int lane = tid & 31;
    const int gid  = lane >> 2;
    const int tig  = lane & 3;
    const int wm   = (w >> 2) * 64;          // 0 / 64
    const int wn   = (w & 3)  * 32;          // 0 / 32 / 64 / 96

    float acc[4][4][4];
    #pragma unroll
    for (int i = 0; i < 4; i++)
        #pragma unroll
        for (int j = 0; j < 4; j++)
            #pragma unroll
            for (int q = 0; q < 4; q++) acc[i][j][q] = 0.f;

    uint4 ra0 = ld_cvt4(gA);
    uint4 ra1 = ld_cvt4(gA + 64 * C_DIM);
    uint4 rb0 = ld_cvt4(gB);
    uint4 rb1 = ld_cvt4(gB + 64 * C_DIM);

    #pragma unroll 1
    for (int it = 0; it < 32; it++) {
        unsigned* bA = sA[it & 1];
        unsigned* bB = sB[it & 1];
        sts_perm(bA, lrow,      lc4, ra0);
        sts_perm(bA, lrow + 64, lc4, ra1);
        sts_perm(bB, lrow,      lc4, rb0);
        sts_perm(bB, lrow + 64, lc4, rb1);
        __syncthreads();

        if (it < 31) {
            const float* nA = gA + (it + 1) * 16;
            const float* nB = gB + (it + 1) * 16;
            ra0 = ld_cvt4(nA);
            ra1 = ld_cvt4(nA + 64 * C_DIM);
            rb0 = ld_cvt4(nB);
            rb1 = ld_cvt4(nB + 64 * C_DIM);
        }

        const unsigned* pa = bA + (wm + gid) * PITCH + (tig << 2);
        const unsigned* pb = bB + (wn + gid) * PITCH + (tig << 2);

        uint4 b4[4];
        #pragma unroll
        for (int ni = 0; ni < 4; ni++)
            b4[ni] = *(const uint4*)(pb + ni * 8 * PITCH);

        #pragma unroll
        for (int mi = 0; mi < 4; mi++) {
            uint4 alo = *(const uint4*)(pa + (mi * 16)     * PITCH);
            uint4 ahi = *(const uint4*)(pa + (mi * 16 + 8) * PITCH);
            #pragma unroll
            for (int ni = 0; ni < 4; ni++) {
                // kk = 0..7   (a0,a1,a2,a3) = (lo.x, hi.x, lo.y, hi.y)
                mma_tf32(acc[mi][ni], alo.x, ahi.x, alo.y, ahi.y, b4[ni].x, b4[ni].y);
                // kk = 8..15
                mma_tf32(acc[mi][ni], alo.z, ahi.z, alo.w, ahi.w, b4[ni].z, b4[ni].w);
            }
        }
    }

    // epilogue: c0=(gid,2tig) c1=(gid,2tig+1) c2=(gid+8,2tig) c3=(gid+8,2tig+1)
    const bool has_bias = (bias != nullptr);
    #pragma unroll
    for (int mi = 0; mi < 4; mi++) {
        #pragma unroll
        for (int ni = 0; ni < 4; ni++) {
            int r0 = m0 + wm + mi * 16 + gid;
            int cc = n0 + wn + ni * 8 + (tig << 1);
            float b0v = has_bias ? bias[cc]     : 0.f;
            float b1v = has_bias ? bias[cc + 1] : 0.f;
            float2 lo = make_float2(acc[mi][ni][0] * scale + b0v,
                                    acc[mi][ni][1] * scale + b1v);
            float2 hi = make_float2(acc[mi][ni][2] * scale + b0v,
                                    acc[mi][ni][3] * scale + b1v);
            *(float2*)&C[(size_t)r0       * C_DIM + cc] = lo;
            *(float2*)&C[(size_t)(r0 + 8) * C_DIM + cc] = hi;
        }
    }
}

// ============================================================================
// Kernel 2: per-pixel two-stage attention (unchanged from passing R8 kernel).
// ============================================================================
__global__ __launch_bounds__(64) void attn_kernel()
{
    __shared__ float qsp[8][68], ksp[8][68], vsp[8][68];
    __shared__ float nfq[8], nfk[8], nfv[8];
    __shared__ float A1raw[8][8];
    __shared__ float A1q[8][8], A1k[8][8];
    __shared__ float q2s[8][68], k2s[8][68];
    __shared__ float attnS[64][65];

    const int t = threadIdx.x;
    const int p = blockIdx.x;
    const float* gq = g_q + (size_t)p * C_DIM;
    const float* gk = g_k + (size_t)p * C_DIM;
    const float* gv = g_v + (size_t)p * C_DIM;

    #pragma unroll
    for (int i = 0; i < 8; i++) {
        qsp[i][t] = gq[i*64 + t];
        ksp[i][t] = gk[i*64 + t];
        vsp[i][t] = gv[i*64 + t];
    }
    __syncthreads();

    if (t < 24) {
        int m = t >> 3, h = t & 7;
        const float* src = (m == 0) ? &qsp[h][0] : (m == 1) ? &ksp[h][0] : &vsp[h][0];
        float ss = 0.f;
        #pragma unroll
        for (int d = 0; d < 64; d += 4) {
            float4 x4 = *(const float4*)&src[d];
            ss += x4.x*x4.x + x4.y*x4.y + x4.z*x4.z + x4.w*x4.w;
        }
        float nf = 1.0f / fmaxf(sqrtf(ss), 1e-12f);
        if (m == 0) nfq[h] = nf; else if (m == 1) nfk[h] = nf; else nfv[h] = nf;
    }
    __syncthreads();

    {
        int h = t >> 3, g = t & 7;
        float dot = 0.f;
        #pragma unroll
        for (int d = 0; d < 64; d += 4) {
            float4 a = *(const float4*)&vsp[h][d];
            float4 b = *(const float4*)&vsp[g][d];
            dot += a.x*b.x + a.y*b.y + a.z*b.z + a.w*b.w;
        }
        A1raw[h][g] = dot * nfv[h] * nfv[g];
    }
    __syncthreads();

    if (t < 8) {
        float r[8]; float mx = -1e30f;
        #pragma unroll
        for (int g = 0; g < 8; g++) { r[g] = A1raw[t][g]; mx = fmaxf(mx, r[g]); }
        float s = 0.f;
        #pragma unroll
        for (int g = 0; g < 8; g++) { r[g] = __expf(r[g] - mx); s += r[g]; }
        float inv = 1.0f / s;
        #pragma unroll
        for (int g = 0; g < 8; g++) {
            float pg = r[g] * inv;
            A1q[t][g] = pg * nfq[g];
            A1k[t][g] = pg * nfk[g];
        }
    }
    __syncthreads();

    {
        float aq[8] = {}, ak[8] = {};
        #pragma unroll
        for (int g = 0; g < 8; g++) {
            float qv = qsp[g][t], kv = ksp[g][t];
            #pragma unroll
            for (int h = 0; h < 8; h++) {
                aq[h] += A1q[h][g] * qv;
                ak[h] += A1k[h][g] * kv;
            }
        }
        #pragma unroll
        for (int h = 0; h < 8; h++) { q2s[h][t] = aq[h]; k2s[h][t] = ak[h]; }
    }
    __syncthreads();

    {
        float row[64];
        #pragma unroll
        for (int e = 0; e < 64; e++) row[e] = 0.f;
        #pragma unroll
        for (int h = 0; h < 8; h++) {
            float kh = k2s[h][t];
            #pragma unroll
            for (int e = 0; e < 64; e += 4) {
                float4 q4 = *(const float4*)&q2s[h][e];
                row[e+0] += kh * q4.x;
                row[e+1] += kh * q4.y;
                row[e+2] += kh * q4.z;
                row[e+3] += kh * q4.w;
            }
        }
        float mx = row[0];
        #pragma unroll
        for (int e = 1; e < 64; e++) mx = fmaxf(mx, row[e]);
        float s = 0.f;
        #pragma unroll
        for (int e = 0; e < 64; e++) { row[e] = __expf(row[e] - mx); s += row[e]; }
        float inv = 1.0f / s;
        #pragma unroll
        for (int e = 0; e < 64; e++) attnS[t][e] = row[e] * inv;
    }
    __syncthreads();

    float o[8] = {};
    #pragma unroll
    for (int d = 0; d < 64; d += 4) {
        float a0 = attnS[d+0][t], a1 = attnS[d+1][t];
        float a2 = attnS[d+2][t], a3 = attnS[d+3][t];
        #pragma unroll
        for (int h = 0; h < 8; h++) {
            float4 v4 = *(const float4*)&vsp[h][d];
            o[h] += v4.x*a0 + v4.y*a1 + v4.z*a2 + v4.w*a3;
        }
    }

    int bIdx = p >> 12;
    int nn   = p & 4095;
    int a    = nn >> 6, r = nn & 63;
    float* dstp = g_mid + (size_t)bIdx * 4096 * C_DIM
                        + ((size_t)t * 64 + a) * C_DIM + (r << 3);
    ((float4*)dstp)[0] = make_float4(o[0], o[1], o[2], o[3]);
    ((float4*)dstp)[1] = make_float4(o[4], o[5], o[6], o[7]);
}

// ============================================================================
extern "C" void kernel_launch(void* const* d_in, const int* in_sizes, int n_in,
                              void* d_out, int out_size)
{
    const float* x  = (const float*)d_in[0];
    const float* Wq = (const float*)d_in[1];
    const float* Wk = (const float*)d_in[2];
    const float* Wv = (const float*)d_in[3];
    // d_in[4] = conv_w : mathematically dead in the reference
    const float* Pw = (const float*)d_in[5];
    const float* Pb = (const float*)d_in[6];
    float* out = (float*)d_out;

    gemm_tf32_kernel<<<512, 256>>>(x, Wq, nullptr, nullptr, 0, 1.0f);
    gemm_tf32_kernel<<<512, 256>>>(x, Wk, nullptr, nullptr, 1, 1.0f);
    gemm_tf32_kernel<<<512, 256>>>(x, Wv, nullptr, nullptr, 2, 2.0f);
    attn_kernel<<<NPIX, 64>>>();
    gemm_tf32_kernel<<<512, 256>>>(nullptr, Pw, Pb, out, 3, 1.0f);
}